// round 1
// baseline (speedup 1.0000x reference)
#include <cuda_runtime.h>
#include <math.h>

#define Bsz 4096
#define Nn 512
#define Mm 64
#define SEQW 8
#define HID 256
#define COUT 128
#define IN_SIZE 73        // SEQW+1+Mm
#define PARAM 70          // M + 1 + 1 + 3 + 1
#define REPR 268          // 2*PARAM + 2*M

// ---------------- scratch (no cudaMalloc allowed) ----------------
__device__ float g_ctrl[Bsz * COUT];     // controller output
__device__ float g_kt[Bsz * 2 * Mm];     // tanh'd keys [b][head][m]
__device__ float g_scal[Bsz * 16];       // per (b,head): knorm,beta,gg,sm0..2,gamma
__device__ float g_ae[Bsz * Mm];         // a - e
__device__ float g_read[Bsz * Mm];       // read vector

__device__ __forceinline__ float lrelu(float x)   { return x > 0.f ? x : 0.01f * x; }
__device__ __forceinline__ float sigmoidf_(float x){ return 1.f / (1.f + __expf(-x)); }
__device__ __forceinline__ float softplusf_(float x){ return x > 20.f ? x : log1pf(expf(x)); }

// ================= Kernel 1: controller + repr (4 rows / block) ============
__global__ void __launch_bounds__(256)
ctrl_kernel(const float* __restrict__ x, const float* __restrict__ prev_read,
            const float* __restrict__ W0, const float* __restrict__ b0,
            const float* __restrict__ W1, const float* __restrict__ b1,
            const float* __restrict__ Wout, const float* __restrict__ bout,
            const float* __restrict__ rW, const float* __restrict__ rb)
{
    __shared__ float cin[4][IN_SIZE];
    __shared__ float h0s[4][HID];
    __shared__ float h1s[4][HID];
    __shared__ float cos_[4][COUT];
    __shared__ float rep[4][REPR];

    const int tid = threadIdx.x;
    const int bbase = blockIdx.x * 4;

    // gather controller input [x(9), prev_read(64)]
    for (int idx = tid; idx < 4 * IN_SIZE; idx += 256) {
        int r = idx / IN_SIZE, c = idx % IN_SIZE;
        int b = bbase + r;
        cin[r][c] = (c < SEQW + 1) ? x[b * (SEQW + 1) + c]
                                   : prev_read[b * Mm + (c - (SEQW + 1))];
    }
    __syncthreads();

    // layer 0: 73 -> 256 (thread j owns output j for all 4 rows)
    {
        int j = tid;
        float a0 = b0[j], a1 = a0, a2 = a0, a3 = a0;
        #pragma unroll 1
        for (int i = 0; i < IN_SIZE; i++) {
            float w = W0[i * HID + j];
            a0 += cin[0][i] * w; a1 += cin[1][i] * w;
            a2 += cin[2][i] * w; a3 += cin[3][i] * w;
        }
        h0s[0][j] = lrelu(a0); h0s[1][j] = lrelu(a1);
        h0s[2][j] = lrelu(a2); h0s[3][j] = lrelu(a3);
    }
    __syncthreads();

    // layer 1: 256 -> 256
    {
        int j = tid;
        float a0 = b1[j], a1 = a0, a2 = a0, a3 = a0;
        #pragma unroll 4
        for (int i = 0; i < HID; i++) {
            float w = W1[i * HID + j];
            a0 += h0s[0][i] * w; a1 += h0s[1][i] * w;
            a2 += h0s[2][i] * w; a3 += h0s[3][i] * w;
        }
        h1s[0][j] = lrelu(a0); h1s[1][j] = lrelu(a1);
        h1s[2][j] = lrelu(a2); h1s[3][j] = lrelu(a3);
    }
    __syncthreads();

    // ctrl out: 256 -> 128, tanh
    if (tid < COUT) {
        int j = tid;
        float a0 = bout[j], a1 = a0, a2 = a0, a3 = a0;
        #pragma unroll 4
        for (int i = 0; i < HID; i++) {
            float w = Wout[i * COUT + j];
            a0 += h1s[0][i] * w; a1 += h1s[1][i] * w;
            a2 += h1s[2][i] * w; a3 += h1s[3][i] * w;
        }
        a0 = tanhf(a0); a1 = tanhf(a1); a2 = tanhf(a2); a3 = tanhf(a3);
        cos_[0][j] = a0; cos_[1][j] = a1; cos_[2][j] = a2; cos_[3][j] = a3;
        g_ctrl[(bbase + 0) * COUT + j] = a0;
        g_ctrl[(bbase + 1) * COUT + j] = a1;
        g_ctrl[(bbase + 2) * COUT + j] = a2;
        g_ctrl[(bbase + 3) * COUT + j] = a3;
    }
    __syncthreads();

    // repr: 128 -> 268
    for (int o = tid; o < REPR; o += 256) {
        float a0 = rb[o], a1 = a0, a2 = a0, a3 = a0;
        #pragma unroll 4
        for (int i = 0; i < COUT; i++) {
            float w = rW[i * REPR + o];
            a0 += cos_[0][i] * w; a1 += cos_[1][i] * w;
            a2 += cos_[2][i] * w; a3 += cos_[3][i] * w;
        }
        rep[0][o] = a0; rep[1][o] = a1; rep[2][o] = a2; rep[3][o] = a3;
    }
    __syncthreads();

    // elementwise transforms in place
    for (int idx = tid; idx < 4 * REPR; idx += 256) {
        int r = idx / REPR, o = idx % REPR;
        float v = rep[r][o], t;
        if (o < 2 * PARAM) {
            int oh = o % PARAM;
            if (oh < Mm)        t = tanhf(v);          // key
            else if (oh == Mm)  t = softplusf_(v);     // beta
            else if (oh == Mm+1)t = sigmoidf_(v);      // g
            else if (oh < Mm+5) t = v;                 // s (softmax later)
            else                t = softplusf_(v)+1.f; // gamma
        } else if (o < 2 * PARAM + Mm) t = sigmoidf_(v);  // e
        else                            t = tanhf(v);     // a
        rep[r][o] = t;
    }
    __syncthreads();

    const int lane = tid & 31, wid = tid >> 5;
    // key store + norm: warp `wid` handles (r = wid>>1, head = wid&1)
    {
        int r = wid >> 1, h = wid & 1, b = bbase + r;
        float v0 = rep[r][h * PARAM + lane];
        float v1 = rep[r][h * PARAM + lane + 32];
        g_kt[b * 128 + h * 64 + lane]      = v0;
        g_kt[b * 128 + h * 64 + lane + 32] = v1;
        float ss = v0 * v0 + v1 * v1;
        #pragma unroll
        for (int o = 16; o; o >>= 1) ss += __shfl_xor_sync(0xffffffffu, ss, o);
        if (lane == 0) g_scal[b * 16 + h * 8 + 0] = sqrtf(ss);
    }
    // scalars: threads 0..7 -> (r,head)
    if (tid < 8) {
        int r = tid >> 1, h = tid & 1, b = bbase + r;
        const float* rp = &rep[r][h * PARAM];
        float* sp = &g_scal[b * 16 + h * 8];
        sp[1] = rp[Mm];       // softplus(beta)
        sp[2] = rp[Mm + 1];   // sigmoid(g)
        sp[6] = rp[Mm + 5];   // softplus(gamma)+1
        float s0 = rp[Mm + 2], s1 = rp[Mm + 3], s2 = rp[Mm + 4];
        float mx = fmaxf(s0, fmaxf(s1, s2));
        float e0 = __expf(s0 - mx), e1 = __expf(s1 - mx), e2 = __expf(s2 - mx);
        float inv = 1.f / (e0 + e1 + e2);
        sp[3] = e0 * inv; sp[4] = e1 * inv; sp[5] = e2 * inv;
    }
    // a - e  (256 threads == 4*64)
    {
        int r = tid >> 6, m = tid & 63;
        g_ae[(bbase + r) * Mm + m] =
            rep[r][2 * PARAM + Mm + m] - rep[r][2 * PARAM + m];
    }
}

// ================= block reduction helper (512 threads) =====================
__device__ __forceinline__ void block_red2(float a, float b, float* oa, float* ob,
                                           float* scratch, bool is_max)
{
    #pragma unroll
    for (int o = 16; o; o >>= 1) {
        float ta = __shfl_xor_sync(0xffffffffu, a, o);
        float tb = __shfl_xor_sync(0xffffffffu, b, o);
        if (is_max) { a = fmaxf(a, ta); b = fmaxf(b, tb); }
        else        { a += ta;          b += tb; }
    }
    int w = threadIdx.x >> 5;
    __syncthreads();
    if ((threadIdx.x & 31) == 0) { scratch[w] = a; scratch[16 + w] = b; }
    __syncthreads();
    if (threadIdx.x < 16) {
        float va = scratch[threadIdx.x];
        float vb = scratch[16 + threadIdx.x];
        #pragma unroll
        for (int o = 8; o; o >>= 1) {
            float ta = __shfl_xor_sync(0xffffu, va, o);
            float tb = __shfl_xor_sync(0xffffu, vb, o);
            if (is_max) { va = fmaxf(va, ta); vb = fmaxf(vb, tb); }
            else        { va += ta;           vb += tb; }
        }
        if (threadIdx.x == 0) { scratch[0] = va; scratch[16] = vb; }
    }
    __syncthreads();
    *oa = scratch[0]; *ob = scratch[16];
}

// ================= Kernel 2: fused addressing + read + bank update ==========
// one CTA per batch element, bank[b] staged once in smem
__global__ void __launch_bounds__(512)
addr_kernel(const float* __restrict__ bank, const float* __restrict__ w_read,
            const float* __restrict__ w_write, float* __restrict__ out)
{
    extern __shared__ float smem[];
    float* sbank = smem;                 // 32768
    float* skt   = sbank + Nn * Mm;      // 128
    float* arr_r = skt + 128;            // 512
    float* arr_w = arr_r + Nn;           // 512
    float* wgr_s = arr_w + Nn;           // 512
    float* wgw_s = wgr_s + Nn;           // 512
    float* aed   = wgw_s + Nn;           // 64
    float* red   = aed + Mm;             // 512
    float* bc    = red + Nn;             // 32

    const int b = blockIdx.x;
    const int tid = threadIdx.x;
    const int lane = tid & 31, wid = tid >> 5;

    // stage bank[b] (128 KB) via float4
    const float4* gb4 = (const float4*)(bank + (size_t)b * Nn * Mm);
    float4* sb4 = (float4*)sbank;
    #pragma unroll
    for (int i = 0; i < 16; i++) sb4[tid + i * 512] = gb4[tid + i * 512];

    if (tid < 128) skt[tid] = g_kt[b * 128 + tid];
    if (tid < 64)  aed[tid] = g_ae[b * 64 + tid];

    const float* sp = &g_scal[b * 16];
    const float knorm_r = sp[0], beta_r = sp[1], gg_r = sp[2];
    const float sm0_r = sp[3], sm1_r = sp[4], sm2_r = sp[5], gam_r = sp[6];
    const float knorm_w = sp[8], beta_w = sp[9], gg_w = sp[10];
    const float sm0_w = sp[11], sm1_w = sp[12], sm2_w = sp[13], gam_w = sp[14];
    __syncthreads();

    // cosine scores for both heads (warp per row)
    for (int n = wid; n < Nn; n += 16) {
        const float* row = sbank + n * Mm;
        float v0 = row[lane], v1 = row[lane + 32];
        float dr = v0 * skt[lane] + v1 * skt[lane + 32];
        float dw = v0 * skt[64 + lane] + v1 * skt[96 + lane];
        float ss = v0 * v0 + v1 * v1;
        #pragma unroll
        for (int o = 16; o; o >>= 1) {
            dr += __shfl_xor_sync(0xffffffffu, dr, o);
            dw += __shfl_xor_sync(0xffffffffu, dw, o);
            ss += __shfl_xor_sync(0xffffffffu, ss, o);
        }
        if (lane == 0) {
            float nb = sqrtf(ss);
            arr_r[n] = beta_r * dr / fmaxf(nb * knorm_r, 1e-8f);
            arr_w[n] = beta_w * dw / fmaxf(nb * knorm_w, 1e-8f);
        }
    }
    __syncthreads();

    // softmax over N (one thread per n), gate interpolation
    float vr = arr_r[tid], vw = arr_w[tid];
    float mr, mw;  block_red2(vr, vw, &mr, &mw, bc, true);
    float er = __expf(vr - mr), ew = __expf(vw - mw);
    float sr, sw;  block_red2(er, ew, &sr, &sw, bc, false);
    float wgr = gg_r * (er / sr) + (1.f - gg_r) * w_read [(size_t)b * Nn + tid];
    float wgw = gg_w * (ew / sw) + (1.f - gg_w) * w_write[(size_t)b * Nn + tid];
    wgr_s[tid] = wgr; wgw_s[tid] = wgw;
    __syncthreads();

    // circular shift (-1,0,1) + sharpen + renormalize
    int nm1 = (tid - 1) & (Nn - 1), np1 = (tid + 1) & (Nn - 1);
    float wsr = wgr_s[nm1] * sm0_r + wgr_s[tid] * sm1_r + wgr_s[np1] * sm2_r;
    float wsw = wgw_s[nm1] * sm0_w + wgw_s[tid] * sm1_w + wgw_s[np1] * sm2_w;
    float pr = powf(wsr, gam_r), pw = powf(wsw, gam_w);
    float spr, spw; block_red2(pr, pw, &spr, &spw, bc, false);
    arr_r[tid] = pr / spr;   // final read weights
    arr_w[tid] = pw / spw;   // final write weights
    __syncthreads();

    // read vector: read[m] = sum_n rw[n]*bank[n,m]
    {
        int c = tid >> 6, m = tid & 63;
        float acc = 0.f;
        int n0 = c * 64;
        #pragma unroll 4
        for (int n = n0; n < n0 + 64; n++) acc += arr_r[n] * sbank[n * Mm + m];
        red[tid] = acc;
    }
    __syncthreads();
    if (tid < 64) {
        float s = 0.f;
        #pragma unroll
        for (int c = 0; c < 8; c++) s += red[c * 64 + tid];
        g_read[b * 64 + tid] = s;
    }

    // new_bank = bank + ww[n]*(a-e)[m]
    float4* ob4 = (float4*)(out + (size_t)Bsz * SEQW + (size_t)b * Nn * Mm);
    #pragma unroll
    for (int i = 0; i < 16; i++) {
        int idx = tid + i * 512;
        float4 v = sb4[idx];
        int n = idx >> 4;
        int mb = (idx & 15) << 2;
        float w = arr_w[n];
        v.x += w * aed[mb];     v.y += w * aed[mb + 1];
        v.z += w * aed[mb + 2]; v.w += w * aed[mb + 3];
        ob4[idx] = v;
    }
}

// ================= Kernel 3: output projection ==============================
__global__ void __launch_bounds__(256)
out_kernel(const float* __restrict__ oW, const float* __restrict__ ob,
           float* __restrict__ out)
{
    __shared__ float sw[(COUT + Mm) * SEQW];  // 192*8
    __shared__ float sb[SEQW];
    for (int i = threadIdx.x; i < (COUT + Mm) * SEQW; i += 256) sw[i] = oW[i];
    if (threadIdx.x < SEQW) sb[threadIdx.x] = ob[threadIdx.x];
    __syncthreads();

    int gid = blockIdx.x * 256 + threadIdx.x;   // Bsz*SEQW total
    int b = gid >> 3, o = gid & 7;
    float acc = sb[o];
    const float* cp = g_ctrl + b * COUT;
    const float* rp = g_read + b * Mm;
    #pragma unroll 4
    for (int i = 0; i < COUT; i++) acc += cp[i] * sw[i * SEQW + o];
    #pragma unroll 4
    for (int i = 0; i < Mm; i++)  acc += rp[i] * sw[(COUT + i) * SEQW + o];
    out[b * SEQW + o] = 1.f / (1.f + __expf(-acc));
}

// ================= launch ====================================================
extern "C" void kernel_launch(void* const* d_in, const int* in_sizes, int n_in,
                              void* d_out, int out_size)
{
    const float* x         = (const float*)d_in[0];
    const float* prev_read = (const float*)d_in[1];
    const float* bank      = (const float*)d_in[2];
    const float* w_read    = (const float*)d_in[3];
    const float* w_write   = (const float*)d_in[4];
    const float* W0        = (const float*)d_in[5];
    const float* b0        = (const float*)d_in[6];
    const float* W1        = (const float*)d_in[7];
    const float* b1        = (const float*)d_in[8];
    const float* Wout      = (const float*)d_in[9];
    const float* bout      = (const float*)d_in[10];
    const float* rW        = (const float*)d_in[11];
    const float* rb        = (const float*)d_in[12];
    const float* oW        = (const float*)d_in[13];
    const float* ob        = (const float*)d_in[14];
    float* out = (float*)d_out;

    const int SMEM2 = (Nn * Mm + 128 + 4 * Nn + Mm + Nn + 32) * (int)sizeof(float);
    cudaFuncSetAttribute(addr_kernel, cudaFuncAttributeMaxDynamicSharedMemorySize, SMEM2);

    ctrl_kernel<<<Bsz / 4, 256>>>(x, prev_read, W0, b0, W1, b1, Wout, bout, rW, rb);
    addr_kernel<<<Bsz, 512, SMEM2>>>(bank, w_read, w_write, out);
    out_kernel<<<Bsz * SEQW / 256, 256>>>(oW, ob, out);
}

// round 2
// speedup vs baseline: 1.5946x; 1.5946x over previous
#include <cuda_runtime.h>
#include <math.h>

#define Bsz 4096
#define Nn 512
#define Mm 64
#define SEQW 8
#define HID 256
#define COUT 128
#define IN_SIZE 73        // SEQW+1+Mm
#define PARAM 70          // M + 1 + 1 + 3 + 1
#define REPR 268          // 2*PARAM + 2*M
#define ROWS 8

// ---------------- scratch (no cudaMalloc allowed) ----------------
__device__ float g_ctrl[Bsz * COUT];     // controller output
__device__ float g_kt[Bsz * 2 * Mm];     // tanh'd keys [b][head][m]
__device__ float g_scal[Bsz * 16];       // per (b,head): knorm,beta,gg,sm0..2,gamma
__device__ float g_ae[Bsz * Mm];         // a - e
__device__ float g_read[Bsz * Mm];       // read vector

__device__ __forceinline__ float lrelu(float x)    { return x > 0.f ? x : 0.01f * x; }
__device__ __forceinline__ float sigmoidf_(float x){ return 1.f / (1.f + __expf(-x)); }
__device__ __forceinline__ float softplusf_(float x){ return x > 20.f ? x : log1pf(expf(x)); }

// ================= Kernel 1: controller + repr (8 rows / block) ============
// activations stored transposed [i][r] so the hot inner loops read them as
// two broadcast float4 LDS per i (8 rows at once).
__global__ void __launch_bounds__(256)
ctrl_kernel(const float* __restrict__ x, const float* __restrict__ prev_read,
            const float* __restrict__ W0, const float* __restrict__ b0,
            const float* __restrict__ W1, const float* __restrict__ b1,
            const float* __restrict__ Wout, const float* __restrict__ bout,
            const float* __restrict__ rW, const float* __restrict__ rb)
{
    __shared__ float cin[IN_SIZE * ROWS];   // [i][r]
    __shared__ float h0s[HID * ROWS];       // [i][r]
    __shared__ float h1s[HID * ROWS];       // [i][r]
    __shared__ float cos_[COUT * ROWS];     // [i][r]
    __shared__ float rep[ROWS][REPR];       // row-major

    const int tid = threadIdx.x;
    const int bbase = blockIdx.x * ROWS;

    // gather controller input [x(9), prev_read(64)] transposed
    for (int idx = tid; idx < IN_SIZE * ROWS; idx += 256) {
        int i = idx >> 3, r = idx & 7;
        int b = bbase + r;
        cin[idx] = (i < SEQW + 1) ? x[b * (SEQW + 1) + i]
                                  : prev_read[b * Mm + (i - (SEQW + 1))];
    }
    __syncthreads();

    // layer 0: 73 -> 256
    {
        int j = tid;
        float bb = b0[j];
        float a0=bb,a1=bb,a2=bb,a3=bb,a4=bb,a5=bb,a6=bb,a7=bb;
        #pragma unroll 4
        for (int i = 0; i < IN_SIZE; i++) {
            float w = W0[i * HID + j];
            float4 hA = *(const float4*)&cin[i * 8];
            float4 hB = *(const float4*)&cin[i * 8 + 4];
            a0 += hA.x*w; a1 += hA.y*w; a2 += hA.z*w; a3 += hA.w*w;
            a4 += hB.x*w; a5 += hB.y*w; a6 += hB.z*w; a7 += hB.w*w;
        }
        *(float4*)&h0s[j*8]   = make_float4(lrelu(a0),lrelu(a1),lrelu(a2),lrelu(a3));
        *(float4*)&h0s[j*8+4] = make_float4(lrelu(a4),lrelu(a5),lrelu(a6),lrelu(a7));
    }
    __syncthreads();

    // layer 1: 256 -> 256
    {
        int j = tid;
        float bb = b1[j];
        float a0=bb,a1=bb,a2=bb,a3=bb,a4=bb,a5=bb,a6=bb,a7=bb;
        #pragma unroll 8
        for (int i = 0; i < HID; i++) {
            float w = W1[i * HID + j];
            float4 hA = *(const float4*)&h0s[i * 8];
            float4 hB = *(const float4*)&h0s[i * 8 + 4];
            a0 += hA.x*w; a1 += hA.y*w; a2 += hA.z*w; a3 += hA.w*w;
            a4 += hB.x*w; a5 += hB.y*w; a6 += hB.z*w; a7 += hB.w*w;
        }
        *(float4*)&h1s[j*8]   = make_float4(lrelu(a0),lrelu(a1),lrelu(a2),lrelu(a3));
        *(float4*)&h1s[j*8+4] = make_float4(lrelu(a4),lrelu(a5),lrelu(a6),lrelu(a7));
    }
    __syncthreads();

    // ctrl out: 256 -> 128, tanh
    if (tid < COUT) {
        int j = tid;
        float bb = bout[j];
        float a0=bb,a1=bb,a2=bb,a3=bb,a4=bb,a5=bb,a6=bb,a7=bb;
        #pragma unroll 8
        for (int i = 0; i < HID; i++) {
            float w = Wout[i * COUT + j];
            float4 hA = *(const float4*)&h1s[i * 8];
            float4 hB = *(const float4*)&h1s[i * 8 + 4];
            a0 += hA.x*w; a1 += hA.y*w; a2 += hA.z*w; a3 += hA.w*w;
            a4 += hB.x*w; a5 += hB.y*w; a6 += hB.z*w; a7 += hB.w*w;
        }
        a0=tanhf(a0); a1=tanhf(a1); a2=tanhf(a2); a3=tanhf(a3);
        a4=tanhf(a4); a5=tanhf(a5); a6=tanhf(a6); a7=tanhf(a7);
        *(float4*)&cos_[j*8]   = make_float4(a0,a1,a2,a3);
        *(float4*)&cos_[j*8+4] = make_float4(a4,a5,a6,a7);
        g_ctrl[(bbase + 0) * COUT + j] = a0;
        g_ctrl[(bbase + 1) * COUT + j] = a1;
        g_ctrl[(bbase + 2) * COUT + j] = a2;
        g_ctrl[(bbase + 3) * COUT + j] = a3;
        g_ctrl[(bbase + 4) * COUT + j] = a4;
        g_ctrl[(bbase + 5) * COUT + j] = a5;
        g_ctrl[(bbase + 6) * COUT + j] = a6;
        g_ctrl[(bbase + 7) * COUT + j] = a7;
    }
    __syncthreads();

    // repr: 128 -> 268
    for (int o = tid; o < REPR; o += 256) {
        float bb = rb[o];
        float a0=bb,a1=bb,a2=bb,a3=bb,a4=bb,a5=bb,a6=bb,a7=bb;
        #pragma unroll 8
        for (int i = 0; i < COUT; i++) {
            float w = rW[i * REPR + o];
            float4 hA = *(const float4*)&cos_[i * 8];
            float4 hB = *(const float4*)&cos_[i * 8 + 4];
            a0 += hA.x*w; a1 += hA.y*w; a2 += hA.z*w; a3 += hA.w*w;
            a4 += hB.x*w; a5 += hB.y*w; a6 += hB.z*w; a7 += hB.w*w;
        }
        rep[0][o]=a0; rep[1][o]=a1; rep[2][o]=a2; rep[3][o]=a3;
        rep[4][o]=a4; rep[5][o]=a5; rep[6][o]=a6; rep[7][o]=a7;
    }
    __syncthreads();

    // elementwise transforms in place
    for (int idx = tid; idx < ROWS * REPR; idx += 256) {
        int r = idx / REPR, o = idx % REPR;
        float v = rep[r][o], t;
        if (o < 2 * PARAM) {
            int oh = o % PARAM;
            if (oh < Mm)        t = tanhf(v);           // key
            else if (oh == Mm)  t = softplusf_(v);      // beta
            else if (oh == Mm+1)t = sigmoidf_(v);       // g
            else if (oh < Mm+5) t = v;                  // s (softmax later)
            else                t = softplusf_(v)+1.f;  // gamma
        } else if (o < 2 * PARAM + Mm) t = sigmoidf_(v); // e
        else                            t = tanhf(v);    // a
        rep[r][o] = t;
    }
    __syncthreads();

    const int lane = tid & 31, wid = tid >> 5;
    // key store + norm: warp `wid` handles row r = wid, both heads
    {
        int r = wid, b = bbase + r;
        #pragma unroll
        for (int h = 0; h < 2; h++) {
            float v0 = rep[r][h * PARAM + lane];
            float v1 = rep[r][h * PARAM + lane + 32];
            g_kt[b * 128 + h * 64 + lane]      = v0;
            g_kt[b * 128 + h * 64 + lane + 32] = v1;
            float ss = v0 * v0 + v1 * v1;
            #pragma unroll
            for (int o = 16; o; o >>= 1) ss += __shfl_xor_sync(0xffffffffu, ss, o);
            if (lane == 0) g_scal[b * 16 + h * 8 + 0] = sqrtf(ss);
        }
    }
    // scalars: threads 0..15 -> (r,head)
    if (tid < 16) {
        int r = tid >> 1, h = tid & 1, b = bbase + r;
        const float* rp = &rep[r][h * PARAM];
        float* sp = &g_scal[b * 16 + h * 8];
        sp[1] = rp[Mm];       // softplus(beta)
        sp[2] = rp[Mm + 1];   // sigmoid(g)
        sp[6] = rp[Mm + 5];   // softplus(gamma)+1
        float s0 = rp[Mm + 2], s1 = rp[Mm + 3], s2 = rp[Mm + 4];
        float mx = fmaxf(s0, fmaxf(s1, s2));
        float e0 = __expf(s0 - mx), e1 = __expf(s1 - mx), e2 = __expf(s2 - mx);
        float inv = 1.f / (e0 + e1 + e2);
        sp[3] = e0 * inv; sp[4] = e1 * inv; sp[5] = e2 * inv;
    }
    // a - e  (8*64 = 512 elems)
    for (int idx = tid; idx < ROWS * Mm; idx += 256) {
        int r = idx >> 6, m = idx & 63;
        g_ae[(bbase + r) * Mm + m] =
            rep[r][2 * PARAM + Mm + m] - rep[r][2 * PARAM + m];
    }
}

// ================= block reduction helper (512 threads) =====================
__device__ __forceinline__ void block_red2(float a, float b, float* oa, float* ob,
                                           float* scratch, bool is_max)
{
    #pragma unroll
    for (int o = 16; o; o >>= 1) {
        float ta = __shfl_xor_sync(0xffffffffu, a, o);
        float tb = __shfl_xor_sync(0xffffffffu, b, o);
        if (is_max) { a = fmaxf(a, ta); b = fmaxf(b, tb); }
        else        { a += ta;          b += tb; }
    }
    int w = threadIdx.x >> 5;
    __syncthreads();
    if ((threadIdx.x & 31) == 0) { scratch[w] = a; scratch[16 + w] = b; }
    __syncthreads();
    if (threadIdx.x < 16) {
        float va = scratch[threadIdx.x];
        float vb = scratch[16 + threadIdx.x];
        #pragma unroll
        for (int o = 8; o; o >>= 1) {
            float ta = __shfl_xor_sync(0xffffu, va, o);
            float tb = __shfl_xor_sync(0xffffu, vb, o);
            if (is_max) { va = fmaxf(va, ta); vb = fmaxf(vb, tb); }
            else        { va += ta;           vb += tb; }
        }
        if (threadIdx.x == 0) { scratch[0] = va; scratch[16] = vb; }
    }
    __syncthreads();
    *oa = scratch[0]; *ob = scratch[16];
}

// ===== Kernel 2: fused addressing + read + bank update (streaming, 2-pass) ==
// one CTA (512 thr, ~17 KB smem) per batch element; bank streamed from
// HBM/L2 twice instead of staged, so 3-4 CTAs/SM keep DRAM saturated.
__global__ void __launch_bounds__(512)
addr_kernel(const float* __restrict__ bank, const float* __restrict__ w_read,
            const float* __restrict__ w_write, float* __restrict__ out)
{
    __shared__ float skt[128];
    __shared__ float sr[Nn], sw_[Nn];     // scores -> final weights
    __shared__ float wgr[Nn], wgw[Nn];
    __shared__ float aed[Mm];
    __shared__ float bc[32];
    __shared__ float red[32 * Mm];        // phase-3 partial read sums

    const int b = blockIdx.x;
    const int tid = threadIdx.x;
    const int lane = tid & 31;

    if (tid < 128) skt[tid] = g_kt[b * 128 + tid];
    if (tid < 64)  aed[tid] = g_ae[b * 64 + tid];

    const float* sp = &g_scal[b * 16];
    const float knorm_r = sp[0], beta_r = sp[1], gg_r = sp[2];
    const float sm0_r = sp[3], sm1_r = sp[4], sm2_r = sp[5], gam_r = sp[6];
    const float knorm_w = sp[8], beta_w = sp[9], gg_w = sp[10];
    const float sm0_w = sp[11], sm1_w = sp[12], sm2_w = sp[13], gam_w = sp[14];
    __syncthreads();

    const int m4 = (tid & 15) * 4;            // fixed m-block per thread
    const float4 ktr = *(const float4*)&skt[m4];
    const float4 ktw = *(const float4*)&skt[64 + m4];
    const float4* gb4 = (const float4*)(bank + (size_t)b * Nn * Mm);

    // ---- pass 1: stream bank -> cosine scores (16-lane groups per row) ----
    #pragma unroll 4
    for (int i = 0; i < 16; i++) {
        int idx = tid + i * 512;
        float4 v = gb4[idx];
        float dr = v.x*ktr.x + v.y*ktr.y + v.z*ktr.z + v.w*ktr.w;
        float dw = v.x*ktw.x + v.y*ktw.y + v.z*ktw.z + v.w*ktw.w;
        float ss = v.x*v.x + v.y*v.y + v.z*v.z + v.w*v.w;
        #pragma unroll
        for (int o = 8; o; o >>= 1) {
            dr += __shfl_xor_sync(0xffffffffu, dr, o);
            dw += __shfl_xor_sync(0xffffffffu, dw, o);
            ss += __shfl_xor_sync(0xffffffffu, ss, o);
        }
        if ((lane & 15) == 0) {
            int n = idx >> 4;
            float nb = sqrtf(ss);
            sr[n]  = beta_r * dr / fmaxf(nb * knorm_r, 1e-8f);
            sw_[n] = beta_w * dw / fmaxf(nb * knorm_w, 1e-8f);
        }
    }
    __syncthreads();

    // ---- softmax over N, gate interpolation ----
    float vr = sr[tid], vw = sw_[tid];
    float mr, mw;  block_red2(vr, vw, &mr, &mw, bc, true);
    float er = __expf(vr - mr), ew = __expf(vw - mw);
    float srr, sww;  block_red2(er, ew, &srr, &sww, bc, false);
    float wgrv = gg_r * (er / srr) + (1.f - gg_r) * w_read [(size_t)b * Nn + tid];
    float wgwv = gg_w * (ew / sww) + (1.f - gg_w) * w_write[(size_t)b * Nn + tid];
    wgr[tid] = wgrv; wgw[tid] = wgwv;
    __syncthreads();

    // ---- circular shift (-1,0,1) + sharpen + renormalize ----
    int nm1 = (tid - 1) & (Nn - 1), np1 = (tid + 1) & (Nn - 1);
    float wsr = wgr[nm1] * sm0_r + wgr[tid] * sm1_r + wgr[np1] * sm2_r;
    float wsw = wgw[nm1] * sm0_w + wgw[tid] * sm1_w + wgw[np1] * sm2_w;
    float pr = powf(wsr, gam_r), pw = powf(wsw, gam_w);
    float spr, spw; block_red2(pr, pw, &spr, &spw, bc, false);
    sr[tid]  = pr / spr;   // final read weights
    sw_[tid] = pw / spw;   // final write weights
    __syncthreads();

    // ---- pass 2: stream bank again -> read vector + new_bank write ----
    const float4 ae4 = *(const float4*)&aed[m4];
    float4 racc = make_float4(0.f, 0.f, 0.f, 0.f);
    float4* ob4 = (float4*)(out + (size_t)Bsz * SEQW + (size_t)b * Nn * Mm);
    #pragma unroll 4
    for (int i = 0; i < 16; i++) {
        int idx = tid + i * 512;
        int n = idx >> 4;
        float4 v = gb4[idx];
        float wwv = sw_[n], wrv = sr[n];
        float4 o_;
        o_.x = v.x + wwv * ae4.x;  o_.y = v.y + wwv * ae4.y;
        o_.z = v.z + wwv * ae4.z;  o_.w = v.w + wwv * ae4.w;
        ob4[idx] = o_;
        racc.x += wrv * v.x;  racc.y += wrv * v.y;
        racc.z += wrv * v.z;  racc.w += wrv * v.w;
    }
    *(float4*)&red[(tid >> 4) * Mm + m4] = racc;
    __syncthreads();
    if (tid < 64) {
        float s = 0.f;
        #pragma unroll
        for (int r = 0; r < 32; r++) s += red[r * Mm + tid];
        g_read[b * Mm + tid] = s;
    }
}

// ================= Kernel 3: output projection ==============================
__global__ void __launch_bounds__(256)
out_kernel(const float* __restrict__ oW, const float* __restrict__ ob,
           float* __restrict__ out)
{
    __shared__ float sw[(COUT + Mm) * SEQW];  // 192*8
    __shared__ float sb[SEQW];
    for (int i = threadIdx.x; i < (COUT + Mm) * SEQW; i += 256) sw[i] = oW[i];
    if (threadIdx.x < SEQW) sb[threadIdx.x] = ob[threadIdx.x];
    __syncthreads();

    int gid = blockIdx.x * 256 + threadIdx.x;   // Bsz*SEQW total
    int b = gid >> 3, o = gid & 7;
    float acc = sb[o];
    const float* cp = g_ctrl + b * COUT;
    const float* rp = g_read + b * Mm;
    #pragma unroll 4
    for (int i = 0; i < COUT; i++) acc += cp[i] * sw[i * SEQW + o];
    #pragma unroll 4
    for (int i = 0; i < Mm; i++)  acc += rp[i] * sw[(COUT + i) * SEQW + o];
    out[b * SEQW + o] = 1.f / (1.f + __expf(-acc));
}

// ================= launch ====================================================
extern "C" void kernel_launch(void* const* d_in, const int* in_sizes, int n_in,
                              void* d_out, int out_size)
{
    const float* x         = (const float*)d_in[0];
    const float* prev_read = (const float*)d_in[1];
    const float* bank      = (const float*)d_in[2];
    const float* w_read    = (const float*)d_in[3];
    const float* w_write   = (const float*)d_in[4];
    const float* W0        = (const float*)d_in[5];
    const float* b0        = (const float*)d_in[6];
    const float* W1        = (const float*)d_in[7];
    const float* b1        = (const float*)d_in[8];
    const float* Wout      = (const float*)d_in[9];
    const float* bout      = (const float*)d_in[10];
    const float* rW        = (const float*)d_in[11];
    const float* rb        = (const float*)d_in[12];
    const float* oW        = (const float*)d_in[13];
    const float* ob        = (const float*)d_in[14];
    float* out = (float*)d_out;

    ctrl_kernel<<<Bsz / ROWS, 256>>>(x, prev_read, W0, b0, W1, b1, Wout, bout, rW, rb);
    addr_kernel<<<Bsz, 512>>>(bank, w_read, w_write, out);
    out_kernel<<<Bsz * SEQW / 256, 256>>>(oW, ob, out);
}

// round 3
// speedup vs baseline: 1.6094x; 1.0093x over previous
#include <cuda_runtime.h>
#include <math.h>

#define Bsz 4096
#define Nn 512
#define Mm 64
#define SEQW 8
#define HID 256
#define COUT 128
#define IN_SIZE 73        // SEQW+1+Mm
#define PARAM 70          // M + 1 + 1 + 3 + 1
#define REPR 268          // 2*PARAM + 2*M
#define ROWS 8

// ---------------- scratch (no cudaMalloc allowed) ----------------
__device__ float g_ctrl[Bsz * COUT];     // controller output
__device__ float g_kt[Bsz * 2 * Mm];     // tanh'd keys [b][head][m]
__device__ float g_scal[Bsz * 16];       // per (b,head): knorm,beta,gg,sm0..2,gamma
__device__ float g_ae[Bsz * Mm];         // a - e
__device__ float g_read[Bsz * Mm];       // read vector

__device__ __forceinline__ float lrelu(float x)    { return x > 0.f ? x : 0.01f * x; }
__device__ __forceinline__ float sigmoidf_(float x){ return 1.f / (1.f + __expf(-x)); }
__device__ __forceinline__ float softplusf_(float x){ return x > 20.f ? x : log1pf(expf(x)); }

// ================= Kernel 1: controller + repr (8 rows, 512 thr, split-K) ===
__global__ void __launch_bounds__(512)
ctrl_kernel(const float* __restrict__ x, const float* __restrict__ prev_read,
            const float* __restrict__ W0, const float* __restrict__ b0,
            const float* __restrict__ W1, const float* __restrict__ b1,
            const float* __restrict__ Wout, const float* __restrict__ bout,
            const float* __restrict__ rW, const float* __restrict__ rb)
{
    __shared__ float cin[IN_SIZE * ROWS];   // [i][r]
    __shared__ float h0s[HID * ROWS];       // [i][r]
    __shared__ float h1s[HID * ROWS];       // [i][r]
    __shared__ float cos_[COUT * ROWS];     // [i][r]
    __shared__ float rep[ROWS][REPR];       // row-major
    __shared__ float psum[4096];            // split-K partials

    const int tid = threadIdx.x;
    const int bbase = blockIdx.x * ROWS;

    // gather controller input [x(9), prev_read(64)] transposed
    for (int idx = tid; idx < IN_SIZE * ROWS; idx += 512) {
        int i = idx >> 3, r = idx & 7;
        int b = bbase + r;
        cin[idx] = (i < SEQW + 1) ? x[b * (SEQW + 1) + i]
                                  : prev_read[b * Mm + (i - (SEQW + 1))];
    }
    __syncthreads();

    // ---- layer 0: 73 -> 256, i split in 2 halves ----
    {
        int j = tid & 255, h = tid >> 8;
        int i0 = h ? 37 : 0, i1 = h ? 73 : 37;
        float a0=0,a1=0,a2=0,a3=0,a4=0,a5=0,a6=0,a7=0;
        #pragma unroll 4
        for (int i = i0; i < i1; i++) {
            float w = W0[i * HID + j];
            float4 hA = *(const float4*)&cin[i * 8];
            float4 hB = *(const float4*)&cin[i * 8 + 4];
            a0 += hA.x*w; a1 += hA.y*w; a2 += hA.z*w; a3 += hA.w*w;
            a4 += hB.x*w; a5 += hB.y*w; a6 += hB.z*w; a7 += hB.w*w;
        }
        *(float4*)&psum[(h*256+j)*8]   = make_float4(a0,a1,a2,a3);
        *(float4*)&psum[(h*256+j)*8+4] = make_float4(a4,a5,a6,a7);
    }
    __syncthreads();
    {   // combine: thread -> (j = tid>>1, quad = tid&1)
        int j = tid >> 1, q = (tid & 1) * 4;
        float4 pA = *(const float4*)&psum[j*8 + q];
        float4 pB = *(const float4*)&psum[(256+j)*8 + q];
        float bb = b0[j];
        *(float4*)&h0s[j*8+q] = make_float4(
            lrelu(pA.x+pB.x+bb), lrelu(pA.y+pB.y+bb),
            lrelu(pA.z+pB.z+bb), lrelu(pA.w+pB.w+bb));
    }
    __syncthreads();

    // ---- layer 1: 256 -> 256, i split in 2 halves ----
    {
        int j = tid & 255, h = tid >> 8;
        int i0 = h * 128, i1 = i0 + 128;
        float a0=0,a1=0,a2=0,a3=0,a4=0,a5=0,a6=0,a7=0;
        #pragma unroll 8
        for (int i = i0; i < i1; i++) {
            float w = W1[i * HID + j];
            float4 hA = *(const float4*)&h0s[i * 8];
            float4 hB = *(const float4*)&h0s[i * 8 + 4];
            a0 += hA.x*w; a1 += hA.y*w; a2 += hA.z*w; a3 += hA.w*w;
            a4 += hB.x*w; a5 += hB.y*w; a6 += hB.z*w; a7 += hB.w*w;
        }
        *(float4*)&psum[(h*256+j)*8]   = make_float4(a0,a1,a2,a3);
        *(float4*)&psum[(h*256+j)*8+4] = make_float4(a4,a5,a6,a7);
    }
    __syncthreads();
    {
        int j = tid >> 1, q = (tid & 1) * 4;
        float4 pA = *(const float4*)&psum[j*8 + q];
        float4 pB = *(const float4*)&psum[(256+j)*8 + q];
        float bb = b1[j];
        *(float4*)&h1s[j*8+q] = make_float4(
            lrelu(pA.x+pB.x+bb), lrelu(pA.y+pB.y+bb),
            lrelu(pA.z+pB.z+bb), lrelu(pA.w+pB.w+bb));
    }
    __syncthreads();

    // ---- ctrl out: 256 -> 128, tanh, i split in 4 quarters ----
    {
        int j = tid & 127, qt = tid >> 7;         // qt 0..3
        int i0 = qt * 64, i1 = i0 + 64;
        float a0=0,a1=0,a2=0,a3=0,a4=0,a5=0,a6=0,a7=0;
        #pragma unroll 8
        for (int i = i0; i < i1; i++) {
            float w = Wout[i * COUT + j];
            float4 hA = *(const float4*)&h1s[i * 8];
            float4 hB = *(const float4*)&h1s[i * 8 + 4];
            a0 += hA.x*w; a1 += hA.y*w; a2 += hA.z*w; a3 += hA.w*w;
            a4 += hB.x*w; a5 += hB.y*w; a6 += hB.z*w; a7 += hB.w*w;
        }
        *(float4*)&psum[(qt*128+j)*8]   = make_float4(a0,a1,a2,a3);
        *(float4*)&psum[(qt*128+j)*8+4] = make_float4(a4,a5,a6,a7);
    }
    __syncthreads();
    if (tid < 256) {   // combine: (j = tid>>1, quad = tid&1)
        int j = tid >> 1, q = (tid & 1) * 4;
        float4 p0 = *(const float4*)&psum[(0*128+j)*8 + q];
        float4 p1 = *(const float4*)&psum[(1*128+j)*8 + q];
        float4 p2 = *(const float4*)&psum[(2*128+j)*8 + q];
        float4 p3 = *(const float4*)&psum[(3*128+j)*8 + q];
        float bb = bout[j];
        float v0 = tanhf(p0.x+p1.x+p2.x+p3.x+bb);
        float v1 = tanhf(p0.y+p1.y+p2.y+p3.y+bb);
        float v2 = tanhf(p0.z+p1.z+p2.z+p3.z+bb);
        float v3 = tanhf(p0.w+p1.w+p2.w+p3.w+bb);
        *(float4*)&cos_[j*8+q] = make_float4(v0,v1,v2,v3);
        int r0 = q;
        g_ctrl[(bbase + r0 + 0) * COUT + j] = v0;
        g_ctrl[(bbase + r0 + 1) * COUT + j] = v1;
        g_ctrl[(bbase + r0 + 2) * COUT + j] = v2;
        g_ctrl[(bbase + r0 + 3) * COUT + j] = v3;
    }
    __syncthreads();

    // ---- repr: 128 -> 268 (268 active threads, full depth) ----
    for (int o = tid; o < REPR; o += 512) {
        float bb = rb[o];
        float a0=bb,a1=bb,a2=bb,a3=bb,a4=bb,a5=bb,a6=bb,a7=bb;
        #pragma unroll 8
        for (int i = 0; i < COUT; i++) {
            float w = rW[i * REPR + o];
            float4 hA = *(const float4*)&cos_[i * 8];
            float4 hB = *(const float4*)&cos_[i * 8 + 4];
            a0 += hA.x*w; a1 += hA.y*w; a2 += hA.z*w; a3 += hA.w*w;
            a4 += hB.x*w; a5 += hB.y*w; a6 += hB.z*w; a7 += hB.w*w;
        }
        rep[0][o]=a0; rep[1][o]=a1; rep[2][o]=a2; rep[3][o]=a3;
        rep[4][o]=a4; rep[5][o]=a5; rep[6][o]=a6; rep[7][o]=a7;
    }
    __syncthreads();

    // elementwise transforms in place
    for (int idx = tid; idx < ROWS * REPR; idx += 512) {
        int r = idx / REPR, o = idx % REPR;
        float v = rep[r][o], t;
        if (o < 2 * PARAM) {
            int oh = o % PARAM;
            if (oh < Mm)        t = tanhf(v);           // key
            else if (oh == Mm)  t = softplusf_(v);      // beta
            else if (oh == Mm+1)t = sigmoidf_(v);       // g
            else if (oh < Mm+5) t = v;                  // s (softmax later)
            else                t = softplusf_(v)+1.f;  // gamma
        } else if (o < 2 * PARAM + Mm) t = sigmoidf_(v); // e
        else                            t = tanhf(v);    // a
        rep[r][o] = t;
    }
    __syncthreads();

    const int lane = tid & 31, wid = tid >> 5;
    // key store + norm: warps 0..7, warp r handles row r, both heads
    if (wid < ROWS) {
        int r = wid, b = bbase + r;
        #pragma unroll
        for (int h = 0; h < 2; h++) {
            float v0 = rep[r][h * PARAM + lane];
            float v1 = rep[r][h * PARAM + lane + 32];
            g_kt[b * 128 + h * 64 + lane]      = v0;
            g_kt[b * 128 + h * 64 + lane + 32] = v1;
            float ss = v0 * v0 + v1 * v1;
            #pragma unroll
            for (int o = 16; o; o >>= 1) ss += __shfl_xor_sync(0xffffffffu, ss, o);
            if (lane == 0) g_scal[b * 16 + h * 8 + 0] = sqrtf(ss);
        }
    }
    // scalars: threads 0..15 -> (r,head)
    if (tid < 16) {
        int r = tid >> 1, h = tid & 1, b = bbase + r;
        const float* rp = &rep[r][h * PARAM];
        float* sp = &g_scal[b * 16 + h * 8];
        sp[1] = rp[Mm];       // softplus(beta)
        sp[2] = rp[Mm + 1];   // sigmoid(g)
        sp[6] = rp[Mm + 5];   // softplus(gamma)+1
        float s0 = rp[Mm + 2], s1 = rp[Mm + 3], s2 = rp[Mm + 4];
        float mx = fmaxf(s0, fmaxf(s1, s2));
        float e0 = __expf(s0 - mx), e1 = __expf(s1 - mx), e2 = __expf(s2 - mx);
        float inv = 1.f / (e0 + e1 + e2);
        sp[3] = e0 * inv; sp[4] = e1 * inv; sp[5] = e2 * inv;
    }
    // a - e  (8*64 = 512 elems)
    {
        int r = tid >> 6, m = tid & 63;
        g_ae[(bbase + r) * Mm + m] =
            rep[r][2 * PARAM + Mm + m] - rep[r][2 * PARAM + m];
    }
}

// ================= block reduction helper (512 threads) =====================
__device__ __forceinline__ void block_red2(float a, float b, float* oa, float* ob,
                                           float* scratch, bool is_max)
{
    #pragma unroll
    for (int o = 16; o; o >>= 1) {
        float ta = __shfl_xor_sync(0xffffffffu, a, o);
        float tb = __shfl_xor_sync(0xffffffffu, b, o);
        if (is_max) { a = fmaxf(a, ta); b = fmaxf(b, tb); }
        else        { a += ta;          b += tb; }
    }
    int w = threadIdx.x >> 5;
    __syncthreads();
    if ((threadIdx.x & 31) == 0) { scratch[w] = a; scratch[16 + w] = b; }
    __syncthreads();
    if (threadIdx.x < 16) {
        float va = scratch[threadIdx.x];
        float vb = scratch[16 + threadIdx.x];
        #pragma unroll
        for (int o = 8; o; o >>= 1) {
            float ta = __shfl_xor_sync(0xffffu, va, o);
            float tb = __shfl_xor_sync(0xffffu, vb, o);
            if (is_max) { va = fmaxf(va, ta); vb = fmaxf(vb, tb); }
            else        { va += ta;           vb += tb; }
        }
        if (threadIdx.x == 0) { scratch[0] = va; scratch[16] = vb; }
    }
    __syncthreads();
    *oa = scratch[0]; *ob = scratch[16];
}

// ===== Kernel 2: fused addressing + read + bank update (single pass) ========
// one CTA (512 thr) per batch element; each thread keeps its 64 bank floats
// in registers across the softmax, so bank is read from DRAM exactly once
// and written exactly once (1.0 GB total, the roofline floor).
__global__ void __launch_bounds__(512)
addr_kernel(const float* __restrict__ bank, const float* __restrict__ w_read,
            const float* __restrict__ w_write, float* __restrict__ out)
{
    __shared__ float skt[128];
    __shared__ float sr[Nn], sw_[Nn];     // scores -> final weights
    __shared__ float wgr[Nn], wgw[Nn];
    __shared__ float aed[Mm];
    __shared__ float bc[32];
    __shared__ float red[32 * Mm];        // partial read sums

    const int b = blockIdx.x;
    const int tid = threadIdx.x;
    const int lane = tid & 31;

    if (tid < 128) skt[tid] = g_kt[b * 128 + tid];
    if (tid < 64)  aed[tid] = g_ae[b * 64 + tid];
    __syncthreads();

    const int m4 = (tid & 15) * 4;            // fixed m-block per thread
    const float4 ktr = *(const float4*)&skt[m4];
    const float4 ktw = *(const float4*)&skt[64 + m4];
    const float4* gb4 = (const float4*)(bank + (size_t)b * Nn * Mm);
    const float* sp = &g_scal[b * 16];

    // ---- load bank slice into registers (16 independent LDG.128) ----
    float4 v[16];
    #pragma unroll
    for (int i = 0; i < 16; i++) v[i] = __ldcs(&gb4[tid + i * 512]);

    // ---- cosine scores (16-lane groups share a row) ----
    {
        const float knorm_r = sp[0], beta_r = sp[1];
        const float knorm_w = sp[8], beta_w = sp[9];
        #pragma unroll
        for (int i = 0; i < 16; i++) {
            float4 x = v[i];
            float dr = x.x*ktr.x + x.y*ktr.y + x.z*ktr.z + x.w*ktr.w;
            float dw = x.x*ktw.x + x.y*ktw.y + x.z*ktw.z + x.w*ktw.w;
            float ss = x.x*x.x + x.y*x.y + x.z*x.z + x.w*x.w;
            #pragma unroll
            for (int o = 8; o; o >>= 1) {
                dr += __shfl_xor_sync(0xffffffffu, dr, o);
                dw += __shfl_xor_sync(0xffffffffu, dw, o);
                ss += __shfl_xor_sync(0xffffffffu, ss, o);
            }
            if ((lane & 15) == 0) {
                int n = (tid >> 4) + i * 32;
                float nb = sqrtf(ss);
                sr[n]  = beta_r * dr / fmaxf(nb * knorm_r, 1e-8f);
                sw_[n] = beta_w * dw / fmaxf(nb * knorm_w, 1e-8f);
            }
        }
    }
    __syncthreads();

    // ---- softmax over N, gate interpolation ----
    {
        const float gg_r = sp[2], gg_w = sp[10];
        float vr = sr[tid], vw = sw_[tid];
        float mr, mw;  block_red2(vr, vw, &mr, &mw, bc, true);
        float er = __expf(vr - mr), ew = __expf(vw - mw);
        float srr, sww;  block_red2(er, ew, &srr, &sww, bc, false);
        float wgrv = gg_r * (er / srr) + (1.f - gg_r) * w_read [(size_t)b * Nn + tid];
        float wgwv = gg_w * (ew / sww) + (1.f - gg_w) * w_write[(size_t)b * Nn + tid];
        wgr[tid] = wgrv; wgw[tid] = wgwv;
    }
    __syncthreads();

    // ---- circular shift (-1,0,1) + sharpen + renormalize ----
    {
        const float sm0_r = sp[3], sm1_r = sp[4], sm2_r = sp[5], gam_r = sp[6];
        const float sm0_w = sp[11], sm1_w = sp[12], sm2_w = sp[13], gam_w = sp[14];
        int nm1 = (tid - 1) & (Nn - 1), np1 = (tid + 1) & (Nn - 1);
        float wsr = wgr[nm1] * sm0_r + wgr[tid] * sm1_r + wgr[np1] * sm2_r;
        float wsw = wgw[nm1] * sm0_w + wgw[tid] * sm1_w + wgw[np1] * sm2_w;
        float pr = powf(wsr, gam_r), pw = powf(wsw, gam_w);
        float spr, spw; block_red2(pr, pw, &spr, &spw, bc, false);
        sr[tid]  = pr / spr;   // final read weights
        sw_[tid] = pw / spw;   // final write weights
    }
    __syncthreads();

    // ---- from registers: read vector + new_bank write ----
    const float4 ae4 = *(const float4*)&aed[m4];
    float4 racc = make_float4(0.f, 0.f, 0.f, 0.f);
    float4* ob4 = (float4*)(out + (size_t)Bsz * SEQW + (size_t)b * Nn * Mm);
    #pragma unroll
    for (int i = 0; i < 16; i++) {
        int n = (tid >> 4) + i * 32;
        float4 x = v[i];
        float wwv = sw_[n], wrv = sr[n];
        float4 o_;
        o_.x = x.x + wwv * ae4.x;  o_.y = x.y + wwv * ae4.y;
        o_.z = x.z + wwv * ae4.z;  o_.w = x.w + wwv * ae4.w;
        __stcs(&ob4[tid + i * 512], o_);
        racc.x += wrv * x.x;  racc.y += wrv * x.y;
        racc.z += wrv * x.z;  racc.w += wrv * x.w;
    }
    *(float4*)&red[(tid >> 4) * Mm + m4] = racc;
    __syncthreads();
    if (tid < 64) {
        float s = 0.f;
        #pragma unroll
        for (int r = 0; r < 32; r++) s += red[r * Mm + tid];
        g_read[b * Mm + tid] = s;
    }
}

// ================= Kernel 3: output projection ==============================
__global__ void __launch_bounds__(256)
out_kernel(const float* __restrict__ oW, const float* __restrict__ ob,
           float* __restrict__ out)
{
    __shared__ float sw[(COUT + Mm) * SEQW];  // 192*8
    __shared__ float sb[SEQW];
    for (int i = threadIdx.x; i < (COUT + Mm) * SEQW; i += 256) sw[i] = oW[i];
    if (threadIdx.x < SEQW) sb[threadIdx.x] = ob[threadIdx.x];
    __syncthreads();

    int gid = blockIdx.x * 256 + threadIdx.x;   // Bsz*SEQW total
    int b = gid >> 3, o = gid & 7;
    float acc = sb[o];
    const float* cp = g_ctrl + b * COUT;
    const float* rp = g_read + b * Mm;
    #pragma unroll 4
    for (int i = 0; i < COUT; i++) acc += cp[i] * sw[i * SEQW + o];
    #pragma unroll 4
    for (int i = 0; i < Mm; i++)  acc += rp[i] * sw[(COUT + i) * SEQW + o];
    out[b * SEQW + o] = 1.f / (1.f + __expf(-acc));
}

// ================= launch ====================================================
extern "C" void kernel_launch(void* const* d_in, const int* in_sizes, int n_in,
                              void* d_out, int out_size)
{
    const float* x         = (const float*)d_in[0];
    const float* prev_read = (const float*)d_in[1];
    const float* bank      = (const float*)d_in[2];
    const float* w_read    = (const float*)d_in[3];
    const float* w_write   = (const float*)d_in[4];
    const float* W0        = (const float*)d_in[5];
    const float* b0        = (const float*)d_in[6];
    const float* W1        = (const float*)d_in[7];
    const float* b1        = (const float*)d_in[8];
    const float* Wout      = (const float*)d_in[9];
    const float* bout      = (const float*)d_in[10];
    const float* rW        = (const float*)d_in[11];
    const float* rb        = (const float*)d_in[12];
    const float* oW        = (const float*)d_in[13];
    const float* ob        = (const float*)d_in[14];
    float* out = (float*)d_out;

    ctrl_kernel<<<Bsz / ROWS, 512>>>(x, prev_read, W0, b0, W1, b1, Wout, bout, rW, rb);
    addr_kernel<<<Bsz, 512>>>(bank, w_read, w_write, out);
    out_kernel<<<Bsz * SEQW / 256, 256>>>(oW, ob, out);
}

// round 4
// speedup vs baseline: 1.9959x; 1.2401x over previous
#include <cuda_runtime.h>
#include <math.h>

#define Bsz 4096
#define Nn 512
#define Mm 64
#define SEQW 8
#define HID 256
#define COUT 128
#define IN_SIZE 73        // SEQW+1+Mm
#define PARAM 70          // M + 1 + 1 + 3 + 1
#define REPR 268          // 2*PARAM + 2*M
#define ROWS 8

// ---------------- scratch (no cudaMalloc allowed) ----------------
__device__ float g_ctrl[Bsz * COUT];     // controller output
__device__ float g_kt[Bsz * 2 * Mm];     // tanh'd keys [b][head][m]
__device__ float g_scal[Bsz * 16];       // per (b,head): knorm,beta,gg,sm0..2,gamma
__device__ float g_ae[Bsz * Mm];         // a - e
__device__ float g_read[Bsz * Mm];       // read vector

__device__ __forceinline__ float lrelu(float x)    { return x > 0.f ? x : 0.01f * x; }
__device__ __forceinline__ float sigmoidf_(float x){ return 1.f / (1.f + __expf(-x)); }
__device__ __forceinline__ float softplusf_(float x){ return x > 20.f ? x : log1pf(expf(x)); }

// ================= Kernel 1: controller + repr (8 rows, 512 thr, split-K) ===
__global__ void __launch_bounds__(512)
ctrl_kernel(const float* __restrict__ x, const float* __restrict__ prev_read,
            const float* __restrict__ W0, const float* __restrict__ b0,
            const float* __restrict__ W1, const float* __restrict__ b1,
            const float* __restrict__ Wout, const float* __restrict__ bout,
            const float* __restrict__ rW, const float* __restrict__ rb)
{
    __shared__ float cin[IN_SIZE * ROWS];   // [i][r]
    __shared__ float h0s[HID * ROWS];       // [i][r]
    __shared__ float h1s[HID * ROWS];       // [i][r]
    __shared__ float cos_[COUT * ROWS];     // [i][r]
    __shared__ float rep[ROWS][REPR];       // row-major
    __shared__ float psum[4096];            // split-K partials

    const int tid = threadIdx.x;
    const int bbase = blockIdx.x * ROWS;

    // gather controller input [x(9), prev_read(64)] transposed
    for (int idx = tid; idx < IN_SIZE * ROWS; idx += 512) {
        int i = idx >> 3, r = idx & 7;
        int b = bbase + r;
        cin[idx] = (i < SEQW + 1) ? x[b * (SEQW + 1) + i]
                                  : prev_read[b * Mm + (i - (SEQW + 1))];
    }
    __syncthreads();

    // ---- layer 0: 73 -> 256, i split in 2 halves ----
    {
        int j = tid & 255, h = tid >> 8;
        int i0 = h ? 37 : 0, i1 = h ? 73 : 37;
        float a0=0,a1=0,a2=0,a3=0,a4=0,a5=0,a6=0,a7=0;
        #pragma unroll 4
        for (int i = i0; i < i1; i++) {
            float w = W0[i * HID + j];
            float4 hA = *(const float4*)&cin[i * 8];
            float4 hB = *(const float4*)&cin[i * 8 + 4];
            a0 += hA.x*w; a1 += hA.y*w; a2 += hA.z*w; a3 += hA.w*w;
            a4 += hB.x*w; a5 += hB.y*w; a6 += hB.z*w; a7 += hB.w*w;
        }
        *(float4*)&psum[(h*256+j)*8]   = make_float4(a0,a1,a2,a3);
        *(float4*)&psum[(h*256+j)*8+4] = make_float4(a4,a5,a6,a7);
    }
    __syncthreads();
    {   // combine
        int j = tid >> 1, q = (tid & 1) * 4;
        float4 pA = *(const float4*)&psum[j*8 + q];
        float4 pB = *(const float4*)&psum[(256+j)*8 + q];
        float bb = b0[j];
        *(float4*)&h0s[j*8+q] = make_float4(
            lrelu(pA.x+pB.x+bb), lrelu(pA.y+pB.y+bb),
            lrelu(pA.z+pB.z+bb), lrelu(pA.w+pB.w+bb));
    }
    __syncthreads();

    // ---- layer 1: 256 -> 256, i split in 2 halves ----
    {
        int j = tid & 255, h = tid >> 8;
        int i0 = h * 128, i1 = i0 + 128;
        float a0=0,a1=0,a2=0,a3=0,a4=0,a5=0,a6=0,a7=0;
        #pragma unroll 8
        for (int i = i0; i < i1; i++) {
            float w = W1[i * HID + j];
            float4 hA = *(const float4*)&h0s[i * 8];
            float4 hB = *(const float4*)&h0s[i * 8 + 4];
            a0 += hA.x*w; a1 += hA.y*w; a2 += hA.z*w; a3 += hA.w*w;
            a4 += hB.x*w; a5 += hB.y*w; a6 += hB.z*w; a7 += hB.w*w;
        }
        *(float4*)&psum[(h*256+j)*8]   = make_float4(a0,a1,a2,a3);
        *(float4*)&psum[(h*256+j)*8+4] = make_float4(a4,a5,a6,a7);
    }
    __syncthreads();
    {
        int j = tid >> 1, q = (tid & 1) * 4;
        float4 pA = *(const float4*)&psum[j*8 + q];
        float4 pB = *(const float4*)&psum[(256+j)*8 + q];
        float bb = b1[j];
        *(float4*)&h1s[j*8+q] = make_float4(
            lrelu(pA.x+pB.x+bb), lrelu(pA.y+pB.y+bb),
            lrelu(pA.z+pB.z+bb), lrelu(pA.w+pB.w+bb));
    }
    __syncthreads();

    // ---- ctrl out: 256 -> 128, tanh, i split in 4 quarters ----
    {
        int j = tid & 127, qt = tid >> 7;         // qt 0..3
        int i0 = qt * 64, i1 = i0 + 64;
        float a0=0,a1=0,a2=0,a3=0,a4=0,a5=0,a6=0,a7=0;
        #pragma unroll 8
        for (int i = i0; i < i1; i++) {
            float w = Wout[i * COUT + j];
            float4 hA = *(const float4*)&h1s[i * 8];
            float4 hB = *(const float4*)&h1s[i * 8 + 4];
            a0 += hA.x*w; a1 += hA.y*w; a2 += hA.z*w; a3 += hA.w*w;
            a4 += hB.x*w; a5 += hB.y*w; a6 += hB.z*w; a7 += hB.w*w;
        }
        *(float4*)&psum[(qt*128+j)*8]   = make_float4(a0,a1,a2,a3);
        *(float4*)&psum[(qt*128+j)*8+4] = make_float4(a4,a5,a6,a7);
    }
    __syncthreads();
    if (tid < 256) {
        int j = tid >> 1, q = (tid & 1) * 4;
        float4 p0 = *(const float4*)&psum[(0*128+j)*8 + q];
        float4 p1 = *(const float4*)&psum[(1*128+j)*8 + q];
        float4 p2 = *(const float4*)&psum[(2*128+j)*8 + q];
        float4 p3 = *(const float4*)&psum[(3*128+j)*8 + q];
        float bb = bout[j];
        float v0 = tanhf(p0.x+p1.x+p2.x+p3.x+bb);
        float v1 = tanhf(p0.y+p1.y+p2.y+p3.y+bb);
        float v2 = tanhf(p0.z+p1.z+p2.z+p3.z+bb);
        float v3 = tanhf(p0.w+p1.w+p2.w+p3.w+bb);
        *(float4*)&cos_[j*8+q] = make_float4(v0,v1,v2,v3);
        int r0 = q;
        g_ctrl[(bbase + r0 + 0) * COUT + j] = v0;
        g_ctrl[(bbase + r0 + 1) * COUT + j] = v1;
        g_ctrl[(bbase + r0 + 2) * COUT + j] = v2;
        g_ctrl[(bbase + r0 + 3) * COUT + j] = v3;
    }
    __syncthreads();

    // ---- repr: 128 -> 268 ----
    for (int o = tid; o < REPR; o += 512) {
        float bb = rb[o];
        float a0=bb,a1=bb,a2=bb,a3=bb,a4=bb,a5=bb,a6=bb,a7=bb;
        #pragma unroll 8
        for (int i = 0; i < COUT; i++) {
            float w = rW[i * REPR + o];
            float4 hA = *(const float4*)&cos_[i * 8];
            float4 hB = *(const float4*)&cos_[i * 8 + 4];
            a0 += hA.x*w; a1 += hA.y*w; a2 += hA.z*w; a3 += hA.w*w;
            a4 += hB.x*w; a5 += hB.y*w; a6 += hB.z*w; a7 += hB.w*w;
        }
        rep[0][o]=a0; rep[1][o]=a1; rep[2][o]=a2; rep[3][o]=a3;
        rep[4][o]=a4; rep[5][o]=a5; rep[6][o]=a6; rep[7][o]=a7;
    }
    __syncthreads();

    // elementwise transforms in place
    for (int idx = tid; idx < ROWS * REPR; idx += 512) {
        int r = idx / REPR, o = idx % REPR;
        float v = rep[r][o], t;
        if (o < 2 * PARAM) {
            int oh = o % PARAM;
            if (oh < Mm)        t = tanhf(v);
            else if (oh == Mm)  t = softplusf_(v);
            else if (oh == Mm+1)t = sigmoidf_(v);
            else if (oh < Mm+5) t = v;
            else                t = softplusf_(v)+1.f;
        } else if (o < 2 * PARAM + Mm) t = sigmoidf_(v);
        else                            t = tanhf(v);
        rep[r][o] = t;
    }
    __syncthreads();

    const int lane = tid & 31, wid = tid >> 5;
    if (wid < ROWS) {
        int r = wid, b = bbase + r;
        #pragma unroll
        for (int h = 0; h < 2; h++) {
            float v0 = rep[r][h * PARAM + lane];
            float v1 = rep[r][h * PARAM + lane + 32];
            g_kt[b * 128 + h * 64 + lane]      = v0;
            g_kt[b * 128 + h * 64 + lane + 32] = v1;
            float ss = v0 * v0 + v1 * v1;
            #pragma unroll
            for (int o = 16; o; o >>= 1) ss += __shfl_xor_sync(0xffffffffu, ss, o);
            if (lane == 0) g_scal[b * 16 + h * 8 + 0] = sqrtf(ss);
        }
    }
    if (tid < 16) {
        int r = tid >> 1, h = tid & 1, b = bbase + r;
        const float* rp = &rep[r][h * PARAM];
        float* sp = &g_scal[b * 16 + h * 8];
        sp[1] = rp[Mm];
        sp[2] = rp[Mm + 1];
        sp[6] = rp[Mm + 5];
        float s0 = rp[Mm + 2], s1 = rp[Mm + 3], s2 = rp[Mm + 4];
        float mx = fmaxf(s0, fmaxf(s1, s2));
        float e0 = __expf(s0 - mx), e1 = __expf(s1 - mx), e2 = __expf(s2 - mx);
        float inv = 1.f / (e0 + e1 + e2);
        sp[3] = e0 * inv; sp[4] = e1 * inv; sp[5] = e2 * inv;
    }
    {
        int r = tid >> 6, m = tid & 63;
        g_ae[(bbase + r) * Mm + m] =
            rep[r][2 * PARAM + Mm + m] - rep[r][2 * PARAM + m];
    }
}

// ================= block reduction helper (512 threads) =====================
__device__ __forceinline__ void block_red2(float a, float b, float* oa, float* ob,
                                           float* scratch, bool is_max)
{
    #pragma unroll
    for (int o = 16; o; o >>= 1) {
        float ta = __shfl_xor_sync(0xffffffffu, a, o);
        float tb = __shfl_xor_sync(0xffffffffu, b, o);
        if (is_max) { a = fmaxf(a, ta); b = fmaxf(b, tb); }
        else        { a += ta;          b += tb; }
    }
    int w = threadIdx.x >> 5;
    __syncthreads();
    if ((threadIdx.x & 31) == 0) { scratch[w] = a; scratch[16 + w] = b; }
    __syncthreads();
    if (threadIdx.x < 16) {
        float va = scratch[threadIdx.x];
        float vb = scratch[16 + threadIdx.x];
        #pragma unroll
        for (int o = 8; o; o >>= 1) {
            float ta = __shfl_xor_sync(0xffffu, va, o);
            float tb = __shfl_xor_sync(0xffffu, vb, o);
            if (is_max) { va = fmaxf(va, ta); vb = fmaxf(vb, tb); }
            else        { va += ta;           vb += tb; }
        }
        if (threadIdx.x == 0) { scratch[0] = va; scratch[16] = vb; }
    }
    __syncthreads();
    *oa = scratch[0]; *ob = scratch[16];
}

// ===== Kernel 2: fused addressing + read + bank update (2-pass streaming) ===
// one CTA (512 thr, ~17 KB smem, low regs) per batch element -> 4 CTAs/SM.
// pass 1: 8 lanes per row (2 consecutive float4/thread) -> only 3 shuffle
// rounds per 32B streamed (5x fewer shuffles than 16-lane layout).
// pass 2 re-reads bank; with ~74 MB of concurrent working set it hits L2.
__global__ void __launch_bounds__(512)
addr_kernel(const float* __restrict__ bank, const float* __restrict__ w_read,
            const float* __restrict__ w_write, float* __restrict__ out)
{
    __shared__ float skt[128];
    __shared__ float sr[Nn], sw_[Nn];     // scores -> final weights
    __shared__ float wgr[Nn], wgw[Nn];
    __shared__ float aed[Mm];
    __shared__ float bc[32];
    __shared__ float red[32 * Mm];        // partial read sums

    const int b = blockIdx.x;
    const int tid = threadIdx.x;

    if (tid < 128) skt[tid] = g_kt[b * 128 + tid];
    if (tid < 64)  aed[tid] = g_ae[b * 64 + tid];
    __syncthreads();

    const float4* gb4 = (const float4*)(bank + (size_t)b * Nn * Mm);
    const float* sp = &g_scal[b * 16];

    // ---- pass 1: stream bank -> cosine scores (8-lane groups per row) ----
    {
        const int g8 = tid >> 3;           // row-group 0..63
        const int mo = (tid & 7) * 8;      // m offset (floats)
        const float4 ktr0 = *(const float4*)&skt[mo];
        const float4 ktr1 = *(const float4*)&skt[mo + 4];
        const float4 ktw0 = *(const float4*)&skt[64 + mo];
        const float4 ktw1 = *(const float4*)&skt[64 + mo + 4];
        const float knorm_r = sp[0], beta_r = sp[1];
        const float knorm_w = sp[8], beta_w = sp[9];
        #pragma unroll 2
        for (int it = 0; it < 8; it++) {
            int n = it * 64 + g8;
            const float4* row = gb4 + n * 16 + (mo >> 2);
            float4 x0 = __ldcg(&row[0]);
            float4 x1 = __ldcg(&row[1]);
            float dr = x0.x*ktr0.x + x0.y*ktr0.y + x0.z*ktr0.z + x0.w*ktr0.w
                     + x1.x*ktr1.x + x1.y*ktr1.y + x1.z*ktr1.z + x1.w*ktr1.w;
            float dw = x0.x*ktw0.x + x0.y*ktw0.y + x0.z*ktw0.z + x0.w*ktw0.w
                     + x1.x*ktw1.x + x1.y*ktw1.y + x1.z*ktw1.z + x1.w*ktw1.w;
            float ss = x0.x*x0.x + x0.y*x0.y + x0.z*x0.z + x0.w*x0.w
                     + x1.x*x1.x + x1.y*x1.y + x1.z*x1.z + x1.w*x1.w;
            #pragma unroll
            for (int o = 4; o; o >>= 1) {
                dr += __shfl_xor_sync(0xffffffffu, dr, o);
                dw += __shfl_xor_sync(0xffffffffu, dw, o);
                ss += __shfl_xor_sync(0xffffffffu, ss, o);
            }
            if ((tid & 7) == 0) {
                float nb = sqrtf(ss);
                sr[n]  = beta_r * dr / fmaxf(nb * knorm_r, 1e-8f);
                sw_[n] = beta_w * dw / fmaxf(nb * knorm_w, 1e-8f);
            }
        }
    }
    __syncthreads();

    // ---- softmax over N, gate interpolation ----
    {
        const float gg_r = sp[2], gg_w = sp[10];
        float vr = sr[tid], vw = sw_[tid];
        float mr, mw;  block_red2(vr, vw, &mr, &mw, bc, true);
        float er = __expf(vr - mr), ew = __expf(vw - mw);
        float srr, sww;  block_red2(er, ew, &srr, &sww, bc, false);
        float wgrv = gg_r * (er / srr) + (1.f - gg_r) * w_read [(size_t)b * Nn + tid];
        float wgwv = gg_w * (ew / sww) + (1.f - gg_w) * w_write[(size_t)b * Nn + tid];
        wgr[tid] = wgrv; wgw[tid] = wgwv;
    }
    __syncthreads();

    // ---- circular shift (-1,0,1) + sharpen + renormalize ----
    {
        const float sm0_r = sp[3], sm1_r = sp[4], sm2_r = sp[5], gam_r = sp[6];
        const float sm0_w = sp[11], sm1_w = sp[12], sm2_w = sp[13], gam_w = sp[14];
        int nm1 = (tid - 1) & (Nn - 1), np1 = (tid + 1) & (Nn - 1);
        float wsr = wgr[nm1] * sm0_r + wgr[tid] * sm1_r + wgr[np1] * sm2_r;
        float wsw = wgw[nm1] * sm0_w + wgw[tid] * sm1_w + wgw[np1] * sm2_w;
        float pr = powf(wsr, gam_r), pw = powf(wsw, gam_w);
        float spr, spw; block_red2(pr, pw, &spr, &spw, bc, false);
        sr[tid]  = pr / spr;   // final read weights
        sw_[tid] = pw / spw;   // final write weights
    }
    __syncthreads();

    // ---- pass 2: re-stream bank (L2 hits) -> read vector + new_bank ----
    {
        const int m4 = (tid & 15) * 4;
        const float4 ae4 = *(const float4*)&aed[m4];
        float4 racc = make_float4(0.f, 0.f, 0.f, 0.f);
        float4* ob4 = (float4*)(out + (size_t)Bsz * SEQW + (size_t)b * Nn * Mm);
        #pragma unroll 4
        for (int i = 0; i < 16; i++) {
            int idx = tid + i * 512;
            int n = idx >> 4;
            float4 x = __ldcg(&gb4[idx]);
            float wwv = sw_[n], wrv = sr[n];
            float4 o_;
            o_.x = x.x + wwv * ae4.x;  o_.y = x.y + wwv * ae4.y;
            o_.z = x.z + wwv * ae4.z;  o_.w = x.w + wwv * ae4.w;
            __stcs(&ob4[idx], o_);
            racc.x += wrv * x.x;  racc.y += wrv * x.y;
            racc.z += wrv * x.z;  racc.w += wrv * x.w;
        }
        *(float4*)&red[(tid >> 4) * Mm + m4] = racc;
    }
    __syncthreads();
    if (tid < 64) {
        float s = 0.f;
        #pragma unroll
        for (int r = 0; r < 32; r++) s += red[r * Mm + tid];
        g_read[b * Mm + tid] = s;
    }
}

// ================= Kernel 3: output projection ==============================
__global__ void __launch_bounds__(256)
out_kernel(const float* __restrict__ oW, const float* __restrict__ ob,
           float* __restrict__ out)
{
    __shared__ float sw[(COUT + Mm) * SEQW];  // 192*8
    __shared__ float sb[SEQW];
    for (int i = threadIdx.x; i < (COUT + Mm) * SEQW; i += 256) sw[i] = oW[i];
    if (threadIdx.x < SEQW) sb[threadIdx.x] = ob[threadIdx.x];
    __syncthreads();

    int gid = blockIdx.x * 256 + threadIdx.x;   // Bsz*SEQW total
    int b = gid >> 3, o = gid & 7;
    float acc = sb[o];
    const float* cp = g_ctrl + b * COUT;
    const float* rp = g_read + b * Mm;
    #pragma unroll 4
    for (int i = 0; i < COUT; i++) acc += cp[i] * sw[i * SEQW + o];
    #pragma unroll 4
    for (int i = 0; i < Mm; i++)  acc += rp[i] * sw[(COUT + i) * SEQW + o];
    out[b * SEQW + o] = 1.f / (1.f + __expf(-acc));
}

// ================= launch ====================================================
extern "C" void kernel_launch(void* const* d_in, const int* in_sizes, int n_in,
                              void* d_out, int out_size)
{
    const float* x         = (const float*)d_in[0];
    const float* prev_read = (const float*)d_in[1];
    const float* bank      = (const float*)d_in[2];
    const float* w_read    = (const float*)d_in[3];
    const float* w_write   = (const float*)d_in[4];
    const float* W0        = (const float*)d_in[5];
    const float* b0        = (const float*)d_in[6];
    const float* W1        = (const float*)d_in[7];
    const float* b1        = (const float*)d_in[8];
    const float* Wout      = (const float*)d_in[9];
    const float* bout      = (const float*)d_in[10];
    const float* rW        = (const float*)d_in[11];
    const float* rb        = (const float*)d_in[12];
    const float* oW        = (const float*)d_in[13];
    const float* ob        = (const float*)d_in[14];
    float* out = (float*)d_out;

    ctrl_kernel<<<Bsz / ROWS, 512>>>(x, prev_read, W0, b0, W1, b1, Wout, bout, rW, rb);
    addr_kernel<<<Bsz, 512>>>(bank, w_read, w_write, out);
    out_kernel<<<Bsz * SEQW / 256, 256>>>(oW, ob, out);
}